// round 11
// baseline (speedup 1.0000x reference)
#include <cuda_runtime.h>
#include <cstdint>
#include <cstddef>

#define N_SIMP 8192
#define KF 8
#define BATCH 64
#define FEAT 128

// ---- kernel 1 tiling: wL = W @ L ----
#define SEG1 16                    // row segments (partial slices)
#define ROWS1 (N_SIMP / SEG1)      // 512 rows per segment
#define COLB1 16                   // column blocks
#define COLS1 (N_SIMP / COLB1)     // 512 cols per block = 128 thr * 4

// ---- kernel 2 tiling: out = wL @ x[b] ----
#define SEG2 8                     // n segments
#define ROWS2 (N_SIMP / SEG2)      // 1024 n per segment

typedef unsigned long long ull;

// Scratch (device globals: allocation-free rule)
__device__ float g_wL_part[SEG1][KF][N_SIMP];          // 4 MB
__device__ float g_wL[KF][N_SIMP];                     // 256 KB
__device__ float g_acc_part[SEG2][KF][BATCH][FEAT];    // 2 MB

__device__ __forceinline__ ull pack_dup(float a) {
    ull r; asm("mov.b64 %0, {%1, %1};" : "=l"(r) : "f"(a)); return r;
}
__device__ __forceinline__ void fma2(ull& d, ull a, ull b) {
    // packed f32x2 FMA: d = a*b + d on both halves (FFMA2 in SASS)
    asm("fma.rn.f32x2 %0, %1, %2, %0;" : "+l"(d) : "l"(a), "l"(b));
}
__device__ __forceinline__ float2 unpack2(ull v) {
    float2 r; asm("mov.b64 {%0, %1}, %2;" : "=f"(r.x), "=f"(r.y) : "l"(v)); return r;
}

// ============================================================
// k1: partial wL. Block = (colb, seg), 256 CTAs, 6 CTAs/SM.
// Thread owns 4 contiguous L columns, all 8 filters (4 k-pairs).
// 8-slot rotating load buffer: each slot reloaded right after use,
// ~8 LDG.128 in flight per warp continuously, only 32 buffer regs.
// ============================================================
__global__ __launch_bounds__(128, 6) void k1_wl(const float* __restrict__ W,
                                                const float* __restrict__ L) {
    const int tid  = threadIdx.x;
    const int colb = blockIdx.x;
    const int seg  = blockIdx.y;
    const int c0   = colb * COLS1 + tid * 4;
    const int m0   = seg * ROWS1;

    __shared__ float2 wtp[4][ROWS1];   // 16 KB, W segment as k-pairs
    for (int idx = tid; idx < 4 * ROWS1; idx += 128) {
        int kp = idx >> 9;
        int m  = idx & (ROWS1 - 1);
        wtp[kp][m] = make_float2(W[(2 * kp) * N_SIMP + m0 + m],
                                 W[(2 * kp + 1) * N_SIMP + m0 + m]);
    }
    __syncthreads();

    ull acc[4][4];
    #pragma unroll
    for (int kp = 0; kp < 4; kp++)
        #pragma unroll
        for (int j = 0; j < 4; j++) acc[kp][j] = 0ULL;

    const float* Lp = L + (size_t)m0 * N_SIMP + c0;

    float4 buf[8];
    #pragma unroll
    for (int r = 0; r < 8; r++)
        buf[r] = __ldcs(reinterpret_cast<const float4*>(Lp + (size_t)r * N_SIMP));

    for (int m0i = 0; m0i < ROWS1; m0i += 8) {
        #pragma unroll
        for (int u = 0; u < 8; u++) {
            const int m = m0i + u;
            float4 lv = buf[u];
            if (m + 8 < ROWS1)                       // refill slot immediately
                buf[u] = __ldcs(reinterpret_cast<const float4*>(
                             Lp + (size_t)(m + 8) * N_SIMP));
            ull ld[4] = { pack_dup(lv.x), pack_dup(lv.y),
                          pack_dup(lv.z), pack_dup(lv.w) };
            #pragma unroll
            for (int kp = 0; kp < 4; kp++) {
                ull wp = *reinterpret_cast<const ull*>(&wtp[kp][m]);  // LDS.64 bcast
                #pragma unroll
                for (int j = 0; j < 4; j++) fma2(acc[kp][j], ld[j], wp);
            }
        }
    }

    #pragma unroll
    for (int kp = 0; kp < 4; kp++) {
        float2 v0 = unpack2(acc[kp][0]);
        float2 v1 = unpack2(acc[kp][1]);
        float2 v2 = unpack2(acc[kp][2]);
        float2 v3 = unpack2(acc[kp][3]);
        float4 lo = make_float4(v0.x, v1.x, v2.x, v3.x);
        float4 hi = make_float4(v0.y, v1.y, v2.y, v3.y);
        __stcs(reinterpret_cast<float4*>(&g_wL_part[seg][2 * kp][c0]),     lo);
        __stcs(reinterpret_cast<float4*>(&g_wL_part[seg][2 * kp + 1][c0]), hi);
    }
}

// ============================================================
// k1b: reduce 16 partial segments into g_wL. 32768 float2 threads.
// ============================================================
__global__ __launch_bounds__(128, 1) void k1_reduce() {
    int i = blockIdx.x * 128 + threadIdx.x;           // float2 index, 32768 total
    const float2* base = reinterpret_cast<const float2*>(&g_wL_part[0][0][0]);
    const int seg_stride = KF * N_SIMP / 2;           // 32768 float2 per segment
    float2 s = make_float2(0.f, 0.f);
    #pragma unroll
    for (int pb = 0; pb < SEG1; pb += 8) {
        float2 v[8];
        #pragma unroll
        for (int r = 0; r < 8; r++)
            v[r] = __ldcs(&base[(size_t)(pb + r) * seg_stride + i]);
        #pragma unroll
        for (int r = 0; r < 8; r++) { s.x += v[r].x; s.y += v[r].y; }
    }
    reinterpret_cast<float2*>(&g_wL[0][0])[i] = s;
}

// ============================================================
// k2: partial out accumulation. Block = (b, seg), 512 CTAs, 6/SM.
// 128 threads = 32 f-groups (float4 over FEAT) x 4 n-subgroups.
// 8-slot rotating load buffer (rows strided by 4 within subgroup).
// Epilogue: smem tree-reduce over n-subgroups -> one slice per CTA.
// ============================================================
__global__ __launch_bounds__(128, 6) void k2_out(const float* __restrict__ x) {
    const int tid = threadIdx.x;
    const int fg  = tid & 31;
    const int ng  = tid >> 5;
    const int b   = blockIdx.x;
    const int seg = blockIdx.y;
    const int n0  = seg * ROWS2;

    __shared__ float2 wlp[4][ROWS2];   // 32 KB, k-pairs of wL for this segment
    for (int idx = tid; idx < 4 * ROWS2; idx += 128) {
        int kp = idx >> 10;
        int n  = idx & (ROWS2 - 1);
        wlp[kp][n] = make_float2(g_wL[2 * kp][n0 + n], g_wL[2 * kp + 1][n0 + n]);
    }
    __syncthreads();

    ull acc[4][4];
    #pragma unroll
    for (int kp = 0; kp < 4; kp++)
        #pragma unroll
        for (int j = 0; j < 4; j++) acc[kp][j] = 0ULL;

    // thread's rows: n = ng + 4*t, t = 0..255
    const float* xb = x + ((size_t)b * N_SIMP + n0) * FEAT + fg * 4;

    float4 buf[8];
    #pragma unroll
    for (int t = 0; t < 8; t++)
        buf[t] = __ldcs(reinterpret_cast<const float4*>(
                     xb + (size_t)(ng + 4 * t) * FEAT));

    const int TMAX = ROWS2 / 4;   // 256 rows per thread
    for (int t0 = 0; t0 < TMAX; t0 += 8) {
        #pragma unroll
        for (int u = 0; u < 8; u++) {
            const int t = t0 + u;
            const int n = ng + 4 * t;
            float4 xv = buf[u];
            if (t + 8 < TMAX)                        // refill slot immediately
                buf[u] = __ldcs(reinterpret_cast<const float4*>(
                             xb + (size_t)(n + 32) * FEAT));
            ull xd[4] = { pack_dup(xv.x), pack_dup(xv.y),
                          pack_dup(xv.z), pack_dup(xv.w) };
            #pragma unroll
            for (int kp = 0; kp < 4; kp++) {
                ull wp = *reinterpret_cast<const ull*>(&wlp[kp][n]);   // LDS.64 bcast
                #pragma unroll
                for (int j = 0; j < 4; j++) fma2(acc[kp][j], xd[j], wp);
            }
        }
    }

    // ---- epilogue: reduce over the 4 n-subgroups via smem (2 rounds) ----
    // Buffer: 2 src-groups x 32 fg x 32 floats = 8 KB, overlaid on wlp.
    __syncthreads();
    float (*rbuf)[32][32] = reinterpret_cast<float (*)[32][32]>(&wlp[0][0]);

    float mine[32];
    #pragma unroll
    for (int kp = 0; kp < 4; kp++) {
        #pragma unroll
        for (int j = 0; j < 4; j++) {
            float2 v = unpack2(acc[kp][j]);
            mine[(2 * kp) * 4 + j]     = v.x;
            mine[(2 * kp + 1) * 4 + j] = v.y;
        }
    }

    if (ng >= 2) {
        #pragma unroll
        for (int t = 0; t < 32; t++) rbuf[ng - 2][fg][t] = mine[t];
    }
    __syncthreads();
    if (ng < 2) {
        #pragma unroll
        for (int t = 0; t < 32; t++) mine[t] += rbuf[ng][fg][t];
    }
    __syncthreads();
    if (ng == 1) {
        #pragma unroll
        for (int t = 0; t < 32; t++) rbuf[0][fg][t] = mine[t];
    }
    __syncthreads();
    if (ng == 0) {
        #pragma unroll
        for (int k = 0; k < 8; k++) {
            float4 o = make_float4(mine[k * 4 + 0] + rbuf[0][fg][k * 4 + 0],
                                   mine[k * 4 + 1] + rbuf[0][fg][k * 4 + 1],
                                   mine[k * 4 + 2] + rbuf[0][fg][k * 4 + 2],
                                   mine[k * 4 + 3] + rbuf[0][fg][k * 4 + 3]);
            __stcs(reinterpret_cast<float4*>(&g_acc_part[seg][k][b][fg * 4]), o);
        }
    }
}

// ============================================================
// k3: reduce 8 partials + tanh -> out [K, B, F]. 32768 float2 threads.
// ============================================================
__global__ __launch_bounds__(128, 1) void k3_tanh(float* __restrict__ out) {
    int i = blockIdx.x * 128 + threadIdx.x;           // float2 index, 32768 total
    const float2* base = reinterpret_cast<const float2*>(&g_acc_part[0][0][0][0]);
    const int part_stride = KF * BATCH * FEAT / 2;    // 32768 float2 per partial
    float2 v[SEG2];
    #pragma unroll
    for (int r = 0; r < SEG2; r++)
        v[r] = __ldcs(&base[(size_t)r * part_stride + i]);
    float2 s = make_float2(0.f, 0.f);
    #pragma unroll
    for (int r = 0; r < SEG2; r++) { s.x += v[r].x; s.y += v[r].y; }
    reinterpret_cast<float2*>(out)[i] = make_float2(tanhf(s.x), tanhf(s.y));
}

// ============================================================
extern "C" void kernel_launch(void* const* d_in, const int* in_sizes, int n_in,
                              void* d_out, int out_size) {
    const float* x = (const float*)d_in[0];   // [B, N, F]
    const float* L = (const float*)d_in[1];   // [N, N]
    const float* W = (const float*)d_in[2];   // [K, N]
    float* out = (float*)d_out;               // [K, B, F]

    k1_wl<<<dim3(COLB1, SEG1), 128>>>(W, L);
    k1_reduce<<<256, 128>>>();
    k2_out<<<dim3(BATCH, SEG2), 128>>>(x);
    k3_tanh<<<256, 128>>>(out);
}

// round 16
// speedup vs baseline: 1.5511x; 1.5511x over previous
#include <cuda_runtime.h>
#include <cstdint>
#include <cstddef>

#define N_SIMP 8192
#define KF 8
#define BATCH 64
#define FEAT 128

// ---- kernel 1 tiling: wL = W @ L ----
#define SEG1 16                    // row segments (partial slices)
#define ROWS1 (N_SIMP / SEG1)      // 512 rows per segment
#define COLB1 16                   // column blocks
#define COLS1 (N_SIMP / COLB1)     // 512 cols per block = 128 thr * 4

// ---- kernel 2 tiling: out = wL @ x[b] ----
#define SEG2 8                     // n segments
#define ROWS2 (N_SIMP / SEG2)      // 1024 n per segment

typedef unsigned long long ull;

// Scratch (device globals: allocation-free rule)
__device__ float g_wL_part[SEG1][KF][N_SIMP];          // 4 MB
__device__ float g_wL[KF][N_SIMP];                     // 256 KB
__device__ float g_acc_part[SEG2][KF][BATCH][FEAT];    // 2 MB

__device__ __forceinline__ ull pack_dup(float a) {
    ull r; asm("mov.b64 %0, {%1, %1};" : "=l"(r) : "f"(a)); return r;
}
__device__ __forceinline__ void fma2(ull& d, ull a, ull b) {
    // packed f32x2 FMA: d = a*b + d on both halves (FFMA2 in SASS)
    asm("fma.rn.f32x2 %0, %1, %2, %0;" : "+l"(d) : "l"(a), "l"(b));
}
__device__ __forceinline__ float2 unpack2(ull v) {
    float2 r; asm("mov.b64 {%0, %1}, %2;" : "=f"(r.x), "=f"(r.y) : "l"(v)); return r;
}

// ============================================================
// k1: partial wL. Block = (colb, seg), 256 CTAs.  (verbatim R5)
// Thread owns 4 contiguous L columns, all 8 filters (4 k-pairs).
// Double-buffered 8-row blocks -> sustained MLP ~8.
// ============================================================
__device__ __forceinline__ void k1_compute8(const float4* lv, int mbase,
                                            ull acc[4][4],
                                            const float2 wtp[4][ROWS1]) {
    #pragma unroll
    for (int r = 0; r < 8; r++) {
        ull ld[4] = { pack_dup(lv[r].x), pack_dup(lv[r].y),
                      pack_dup(lv[r].z), pack_dup(lv[r].w) };
        #pragma unroll
        for (int kp = 0; kp < 4; kp++) {
            ull wp = *reinterpret_cast<const ull*>(&wtp[kp][mbase + r]);  // LDS.64 bcast
            #pragma unroll
            for (int j = 0; j < 4; j++) fma2(acc[kp][j], ld[j], wp);
        }
    }
}

__global__ __launch_bounds__(128, 1) void k1_wl(const float* __restrict__ W,
                                                const float* __restrict__ L) {
    const int tid  = threadIdx.x;
    const int colb = blockIdx.x;
    const int seg  = blockIdx.y;
    const int c0   = colb * COLS1 + tid * 4;
    const int m0   = seg * ROWS1;

    __shared__ float2 wtp[4][ROWS1];   // 16 KB, W segment as k-pairs
    for (int idx = tid; idx < 4 * ROWS1; idx += 128) {
        int kp = idx >> 9;
        int m  = idx & (ROWS1 - 1);
        wtp[kp][m] = make_float2(W[(2 * kp) * N_SIMP + m0 + m],
                                 W[(2 * kp + 1) * N_SIMP + m0 + m]);
    }
    __syncthreads();

    ull acc[4][4];
    #pragma unroll
    for (int kp = 0; kp < 4; kp++)
        #pragma unroll
        for (int j = 0; j < 4; j++) acc[kp][j] = 0ULL;

    const float* Lp = L + (size_t)m0 * N_SIMP + c0;

    float4 bufA[8], bufB[8];
    #pragma unroll
    for (int r = 0; r < 8; r++)
        bufA[r] = __ldcs(reinterpret_cast<const float4*>(Lp + (size_t)r * N_SIMP));

    for (int m = 0; m < ROWS1; m += 16) {
        #pragma unroll
        for (int r = 0; r < 8; r++)
            bufB[r] = __ldcs(reinterpret_cast<const float4*>(
                          Lp + (size_t)(m + 8 + r) * N_SIMP));
        k1_compute8(bufA, m, acc, wtp);
        if (m + 16 < ROWS1) {
            #pragma unroll
            for (int r = 0; r < 8; r++)
                bufA[r] = __ldcs(reinterpret_cast<const float4*>(
                              Lp + (size_t)(m + 16 + r) * N_SIMP));
        }
        k1_compute8(bufB, m + 8, acc, wtp);
    }

    #pragma unroll
    for (int kp = 0; kp < 4; kp++) {
        float2 v0 = unpack2(acc[kp][0]);
        float2 v1 = unpack2(acc[kp][1]);
        float2 v2 = unpack2(acc[kp][2]);
        float2 v3 = unpack2(acc[kp][3]);
        float4 lo = make_float4(v0.x, v1.x, v2.x, v3.x);
        float4 hi = make_float4(v0.y, v1.y, v2.y, v3.y);
        __stcs(reinterpret_cast<float4*>(&g_wL_part[seg][2 * kp][c0]),     lo);
        __stcs(reinterpret_cast<float4*>(&g_wL_part[seg][2 * kp + 1][c0]), hi);
    }
}

// ============================================================
// k1b: reduce 16 partial segments into g_wL. 32768 float2 threads.
// ============================================================
__global__ __launch_bounds__(128, 1) void k1_reduce() {
    int i = blockIdx.x * 128 + threadIdx.x;           // float2 index, 32768 total
    const float2* base = reinterpret_cast<const float2*>(&g_wL_part[0][0][0]);
    const int seg_stride = KF * N_SIMP / 2;           // 32768 float2 per segment
    float2 s = make_float2(0.f, 0.f);
    #pragma unroll
    for (int pb = 0; pb < SEG1; pb += 8) {
        float2 v[8];
        #pragma unroll
        for (int r = 0; r < 8; r++)
            v[r] = __ldcs(&base[(size_t)(pb + r) * seg_stride + i]);
        #pragma unroll
        for (int r = 0; r < 8; r++) { s.x += v[r].x; s.y += v[r].y; }
    }
    reinterpret_cast<float2*>(&g_wL[0][0])[i] = s;
}

// ============================================================
// k2: partial out accumulation. Block = (b, seg), 512 CTAs.
// NEW slim datapath: 128 thr = 64 f2-groups x 2 n-subgroups.
// Thread owns 2 feature columns (float2 loads), all 8 filters:
// acc = 8 ull (16 regs), dbuf 2x8 float2 (32 regs) -> ~70 regs
// -> 6 CTAs/SM (24 warps) without spills.
// ============================================================
__global__ __launch_bounds__(128, 6) void k2_out(const float* __restrict__ x) {
    const int tid = threadIdx.x;
    const int fg  = tid & 63;          // float2 group over FEAT
    const int ng  = tid >> 6;          // n-subgroup (0,1)
    const int b   = blockIdx.x;
    const int seg = blockIdx.y;
    const int n0  = seg * ROWS2;

    __shared__ float2 wlp[4][ROWS2];   // 32 KB, k-pairs of wL for this segment
    for (int idx = tid; idx < 4 * ROWS2; idx += 128) {
        int kp = idx >> 10;
        int n  = idx & (ROWS2 - 1);
        wlp[kp][n] = make_float2(g_wL[2 * kp][n0 + n], g_wL[2 * kp + 1][n0 + n]);
    }
    __syncthreads();

    // acc[kp][j]: packed {out[2kp], out[2kp+1]} for feature column f0+j
    ull acc[4][2];
    #pragma unroll
    for (int kp = 0; kp < 4; kp++) {
        acc[kp][0] = 0ULL; acc[kp][1] = 0ULL;
    }

    // thread's rows: n = ng + 2*t, t = 0..511
    const float* xb = x + ((size_t)b * N_SIMP + n0) * FEAT + fg * 2;

    float2 bufA[8], bufB[8];
    #pragma unroll
    for (int r = 0; r < 8; r++)
        bufA[r] = __ldcs(reinterpret_cast<const float2*>(
                      xb + (size_t)(ng + 2 * r) * FEAT));

    const int TMAX = ROWS2 / 2;   // 512 rows per thread
    for (int t0 = 0; t0 < TMAX; t0 += 16) {
        #pragma unroll
        for (int r = 0; r < 8; r++)
            bufB[r] = __ldcs(reinterpret_cast<const float2*>(
                          xb + (size_t)(ng + 2 * (t0 + 8 + r)) * FEAT));
        #pragma unroll
        for (int r = 0; r < 8; r++) {
            const int n = ng + 2 * (t0 + r);
            ull xd0 = pack_dup(bufA[r].x);
            ull xd1 = pack_dup(bufA[r].y);
            #pragma unroll
            for (int kp = 0; kp < 4; kp++) {
                ull wp = *reinterpret_cast<const ull*>(&wlp[kp][n]);   // LDS.64 bcast
                fma2(acc[kp][0], xd0, wp);
                fma2(acc[kp][1], xd1, wp);
            }
        }
        if (t0 + 16 < TMAX) {
            #pragma unroll
            for (int r = 0; r < 8; r++)
                bufA[r] = __ldcs(reinterpret_cast<const float2*>(
                              xb + (size_t)(ng + 2 * (t0 + 16 + r)) * FEAT));
        }
        #pragma unroll
        for (int r = 0; r < 8; r++) {
            const int n = ng + 2 * (t0 + 8 + r);
            ull xd0 = pack_dup(bufB[r].x);
            ull xd1 = pack_dup(bufB[r].y);
            #pragma unroll
            for (int kp = 0; kp < 4; kp++) {
                ull wp = *reinterpret_cast<const ull*>(&wlp[kp][n]);   // LDS.64 bcast
                fma2(acc[kp][0], xd0, wp);
                fma2(acc[kp][1], xd1, wp);
            }
        }
    }

    // ---- epilogue: reduce over the 2 n-subgroups via smem (1 round) ----
    // Per-thread partial = 16 floats (8 k x 2 f). Buffer 64 fg x 16 = 4 KB.
    __syncthreads();
    float (*rbuf)[16] = reinterpret_cast<float (*)[16]>(&wlp[0][0]);

    float mine[16];
    #pragma unroll
    for (int kp = 0; kp < 4; kp++) {
        #pragma unroll
        for (int j = 0; j < 2; j++) {
            float2 v = unpack2(acc[kp][j]);
            mine[(2 * kp) * 2 + j]     = v.x;
            mine[(2 * kp + 1) * 2 + j] = v.y;
        }
    }

    if (ng == 1) {
        #pragma unroll
        for (int t = 0; t < 16; t++) rbuf[fg][t] = mine[t];
    }
    __syncthreads();
    if (ng == 0) {
        #pragma unroll
        for (int k = 0; k < 8; k++) {
            float2 o = make_float2(mine[k * 2 + 0] + rbuf[fg][k * 2 + 0],
                                   mine[k * 2 + 1] + rbuf[fg][k * 2 + 1]);
            __stcs(reinterpret_cast<float2*>(&g_acc_part[seg][k][b][fg * 2]), o);
        }
    }
}

// ============================================================
// k3: reduce 8 partials + tanh -> out [K, B, F]. 32768 float2 threads.
// ============================================================
__global__ __launch_bounds__(128, 1) void k3_tanh(float* __restrict__ out) {
    int i = blockIdx.x * 128 + threadIdx.x;           // float2 index, 32768 total
    const float2* base = reinterpret_cast<const float2*>(&g_acc_part[0][0][0][0]);
    const int part_stride = KF * BATCH * FEAT / 2;    // 32768 float2 per partial
    float2 v[SEG2];
    #pragma unroll
    for (int r = 0; r < SEG2; r++)
        v[r] = __ldcs(&base[(size_t)r * part_stride + i]);
    float2 s = make_float2(0.f, 0.f);
    #pragma unroll
    for (int r = 0; r < SEG2; r++) { s.x += v[r].x; s.y += v[r].y; }
    reinterpret_cast<float2*>(out)[i] = make_float2(tanhf(s.x), tanhf(s.y));
}

// ============================================================
extern "C" void kernel_launch(void* const* d_in, const int* in_sizes, int n_in,
                              void* d_out, int out_size) {
    const float* x = (const float*)d_in[0];   // [B, N, F]
    const float* L = (const float*)d_in[1];   // [N, N]
    const float* W = (const float*)d_in[2];   // [K, N]
    float* out = (float*)d_out;               // [K, B, F]

    k1_wl<<<dim3(COLB1, SEG1), 128>>>(W, L);
    k1_reduce<<<256, 128>>>();
    k2_out<<<dim3(BATCH, SEG2), 128>>>(x);
    k3_tanh<<<256, 128>>>(out);
}

// round 17
// speedup vs baseline: 1.7035x; 1.0982x over previous
#include <cuda_runtime.h>
#include <cstdint>
#include <cstddef>

#define N_SIMP 8192
#define KF 8
#define BATCH 64
#define FEAT 128

// ---- kernel 1 tiling: wL = W @ L ----
#define SEG1 16                    // row segments (partial slices)
#define ROWS1 (N_SIMP / SEG1)      // 512 rows per segment
#define COLB1 16                   // column blocks
#define COLS1 (N_SIMP / COLB1)     // 512 cols per block = 128 thr * 4

// ---- kernel 2 tiling: out = wL @ x[b] ----
#define SEG2 8                     // n segments
#define ROWS2 (N_SIMP / SEG2)      // 1024 n per segment

typedef unsigned long long ull;

// Scratch (device globals: allocation-free rule)
__device__ float g_wL_part[SEG1][KF][N_SIMP];          // 4 MB
__device__ float g_wL[KF][N_SIMP];                     // 256 KB
__device__ float g_acc_part[SEG2][KF][BATCH][FEAT];    // 2 MB

__device__ __forceinline__ ull pack_dup(float a) {
    ull r; asm("mov.b64 %0, {%1, %1};" : "=l"(r) : "f"(a)); return r;
}
__device__ __forceinline__ void fma2(ull& d, ull a, ull b) {
    // packed f32x2 FMA: d = a*b + d on both halves (FFMA2 in SASS)
    asm("fma.rn.f32x2 %0, %1, %2, %0;" : "+l"(d) : "l"(a), "l"(b));
}
__device__ __forceinline__ float2 unpack2(ull v) {
    float2 r; asm("mov.b64 {%0, %1}, %2;" : "=f"(r.x), "=f"(r.y) : "l"(v)); return r;
}

// ============================================================
// k1: partial wL. Block = (colb, seg), 256 CTAs, 4 CTAs/SM.
// Thread owns 4 contiguous L columns, all 8 filters (4 k-pairs).
// Rotating-16 load buffer: slot refilled right after consumption ->
// ~16 LDG.128 pinned in flight per warp, no drain phases.
// ============================================================
__global__ __launch_bounds__(128, 4) void k1_wl(const float* __restrict__ W,
                                                const float* __restrict__ L) {
    const int tid  = threadIdx.x;
    const int colb = blockIdx.x;
    const int seg  = blockIdx.y;
    const int c0   = colb * COLS1 + tid * 4;
    const int m0   = seg * ROWS1;

    __shared__ float2 wtp[4][ROWS1];   // 16 KB, W segment as k-pairs
    for (int idx = tid; idx < 4 * ROWS1; idx += 128) {
        int kp = idx >> 9;
        int m  = idx & (ROWS1 - 1);
        wtp[kp][m] = make_float2(W[(2 * kp) * N_SIMP + m0 + m],
                                 W[(2 * kp + 1) * N_SIMP + m0 + m]);
    }
    __syncthreads();

    ull acc[4][4];
    #pragma unroll
    for (int kp = 0; kp < 4; kp++)
        #pragma unroll
        for (int j = 0; j < 4; j++) acc[kp][j] = 0ULL;

    const float* Lp = L + (size_t)m0 * N_SIMP + c0;

    float4 buf[16];
    #pragma unroll
    for (int r = 0; r < 16; r++)
        buf[r] = __ldcs(reinterpret_cast<const float4*>(Lp + (size_t)r * N_SIMP));

    for (int m0i = 0; m0i < ROWS1; m0i += 16) {
        #pragma unroll
        for (int u = 0; u < 16; u++) {
            const int m = m0i + u;
            float4 lv = buf[u];
            if (m + 16 < ROWS1)                      // refill slot immediately
                buf[u] = __ldcs(reinterpret_cast<const float4*>(
                             Lp + (size_t)(m + 16) * N_SIMP));
            ull ld[4] = { pack_dup(lv.x), pack_dup(lv.y),
                          pack_dup(lv.z), pack_dup(lv.w) };
            #pragma unroll
            for (int kp = 0; kp < 4; kp++) {
                ull wp = *reinterpret_cast<const ull*>(&wtp[kp][m]);  // LDS.64 bcast
                #pragma unroll
                for (int j = 0; j < 4; j++) fma2(acc[kp][j], ld[j], wp);
            }
        }
    }

    #pragma unroll
    for (int kp = 0; kp < 4; kp++) {
        float2 v0 = unpack2(acc[kp][0]);
        float2 v1 = unpack2(acc[kp][1]);
        float2 v2 = unpack2(acc[kp][2]);
        float2 v3 = unpack2(acc[kp][3]);
        float4 lo = make_float4(v0.x, v1.x, v2.x, v3.x);
        float4 hi = make_float4(v0.y, v1.y, v2.y, v3.y);
        __stcs(reinterpret_cast<float4*>(&g_wL_part[seg][2 * kp][c0]),     lo);
        __stcs(reinterpret_cast<float4*>(&g_wL_part[seg][2 * kp + 1][c0]), hi);
    }
}

// ============================================================
// k1b: reduce 16 partial segments into g_wL. 32768 float2 threads.
// ============================================================
__global__ __launch_bounds__(128, 1) void k1_reduce() {
    int i = blockIdx.x * 128 + threadIdx.x;           // float2 index, 32768 total
    const float2* base = reinterpret_cast<const float2*>(&g_wL_part[0][0][0]);
    const int seg_stride = KF * N_SIMP / 2;           // 32768 float2 per segment
    float2 s = make_float2(0.f, 0.f);
    #pragma unroll
    for (int pb = 0; pb < SEG1; pb += 8) {
        float2 v[8];
        #pragma unroll
        for (int r = 0; r < 8; r++)
            v[r] = __ldcs(&base[(size_t)(pb + r) * seg_stride + i]);
        #pragma unroll
        for (int r = 0; r < 8; r++) { s.x += v[r].x; s.y += v[r].y; }
    }
    reinterpret_cast<float2*>(&g_wL[0][0])[i] = s;
}

// ============================================================
// k2: partial out accumulation. Block = (b, seg), 512 CTAs, 4/SM.
// 128 threads = 32 f-groups (float4 over FEAT) x 4 n-subgroups.
// Rotating-16 load buffer (rows strided by 4 within subgroup).
// Epilogue: smem tree-reduce over n-subgroups -> one slice per CTA.
// ============================================================
__global__ __launch_bounds__(128, 4) void k2_out(const float* __restrict__ x) {
    const int tid = threadIdx.x;
    const int fg  = tid & 31;
    const int ng  = tid >> 5;
    const int b   = blockIdx.x;
    const int seg = blockIdx.y;
    const int n0  = seg * ROWS2;

    __shared__ float2 wlp[4][ROWS2];   // 32 KB, k-pairs of wL for this segment
    for (int idx = tid; idx < 4 * ROWS2; idx += 128) {
        int kp = idx >> 10;
        int n  = idx & (ROWS2 - 1);
        wlp[kp][n] = make_float2(g_wL[2 * kp][n0 + n], g_wL[2 * kp + 1][n0 + n]);
    }
    __syncthreads();

    ull acc[4][4];
    #pragma unroll
    for (int kp = 0; kp < 4; kp++)
        #pragma unroll
        for (int j = 0; j < 4; j++) acc[kp][j] = 0ULL;

    // thread's rows: n = ng + 4*t, t = 0..255
    const float* xb = x + ((size_t)b * N_SIMP + n0) * FEAT + fg * 4;

    float4 buf[16];
    #pragma unroll
    for (int t = 0; t < 16; t++)
        buf[t] = __ldcs(reinterpret_cast<const float4*>(
                     xb + (size_t)(ng + 4 * t) * FEAT));

    const int TMAX = ROWS2 / 4;   // 256 rows per thread
    for (int t0 = 0; t0 < TMAX; t0 += 16) {
        #pragma unroll
        for (int u = 0; u < 16; u++) {
            const int t = t0 + u;
            const int n = ng + 4 * t;
            float4 xv = buf[u];
            if (t + 16 < TMAX)                       // refill slot immediately
                buf[u] = __ldcs(reinterpret_cast<const float4*>(
                             xb + (size_t)(n + 64) * FEAT));
            ull xd[4] = { pack_dup(xv.x), pack_dup(xv.y),
                          pack_dup(xv.z), pack_dup(xv.w) };
            #pragma unroll
            for (int kp = 0; kp < 4; kp++) {
                ull wp = *reinterpret_cast<const ull*>(&wlp[kp][n]);   // LDS.64 bcast
                #pragma unroll
                for (int j = 0; j < 4; j++) fma2(acc[kp][j], xd[j], wp);
            }
        }
    }

    // ---- epilogue: reduce over the 4 n-subgroups via smem (2 rounds) ----
    // Buffer: 2 src-groups x 32 fg x 32 floats = 8 KB, overlaid on wlp.
    __syncthreads();
    float (*rbuf)[32][32] = reinterpret_cast<float (*)[32][32]>(&wlp[0][0]);

    float mine[32];
    #pragma unroll
    for (int kp = 0; kp < 4; kp++) {
        #pragma unroll
        for (int j = 0; j < 4; j++) {
            float2 v = unpack2(acc[kp][j]);
            mine[(2 * kp) * 4 + j]     = v.x;
            mine[(2 * kp + 1) * 4 + j] = v.y;
        }
    }

    if (ng >= 2) {
        #pragma unroll
        for (int t = 0; t < 32; t++) rbuf[ng - 2][fg][t] = mine[t];
    }
    __syncthreads();
    if (ng < 2) {
        #pragma unroll
        for (int t = 0; t < 32; t++) mine[t] += rbuf[ng][fg][t];
    }
    __syncthreads();
    if (ng == 1) {
        #pragma unroll
        for (int t = 0; t < 32; t++) rbuf[0][fg][t] = mine[t];
    }
    __syncthreads();
    if (ng == 0) {
        #pragma unroll
        for (int k = 0; k < 8; k++) {
            float4 o = make_float4(mine[k * 4 + 0] + rbuf[0][fg][k * 4 + 0],
                                   mine[k * 4 + 1] + rbuf[0][fg][k * 4 + 1],
                                   mine[k * 4 + 2] + rbuf[0][fg][k * 4 + 2],
                                   mine[k * 4 + 3] + rbuf[0][fg][k * 4 + 3]);
            __stcs(reinterpret_cast<float4*>(&g_acc_part[seg][k][b][fg * 4]), o);
        }
    }
}

// ============================================================
// k3: reduce 8 partials + tanh -> out [K, B, F]. 32768 float2 threads.
// ============================================================
__global__ __launch_bounds__(128, 1) void k3_tanh(float* __restrict__ out) {
    int i = blockIdx.x * 128 + threadIdx.x;           // float2 index, 32768 total
    const float2* base = reinterpret_cast<const float2*>(&g_acc_part[0][0][0][0]);
    const int part_stride = KF * BATCH * FEAT / 2;    // 32768 float2 per partial
    float2 v[SEG2];
    #pragma unroll
    for (int r = 0; r < SEG2; r++)
        v[r] = __ldcs(&base[(size_t)r * part_stride + i]);
    float2 s = make_float2(0.f, 0.f);
    #pragma unroll
    for (int r = 0; r < SEG2; r++) { s.x += v[r].x; s.y += v[r].y; }
    reinterpret_cast<float2*>(out)[i] = make_float2(tanhf(s.x), tanhf(s.y));
}

// ============================================================
extern "C" void kernel_launch(void* const* d_in, const int* in_sizes, int n_in,
                              void* d_out, int out_size) {
    const float* x = (const float*)d_in[0];   // [B, N, F]
    const float* L = (const float*)d_in[1];   // [N, N]
    const float* W = (const float*)d_in[2];   // [K, N]
    float* out = (float*)d_out;               // [K, B, F]

    k1_wl<<<dim3(COLB1, SEG1), 128>>>(W, L);
    k1_reduce<<<256, 128>>>();
    k2_out<<<dim3(BATCH, SEG2), 128>>>(x);
    k3_tanh<<<256, 128>>>(out);
}